// round 8
// baseline (speedup 1.0000x reference)
#include <cuda_runtime.h>
#include <cuda_bf16.h>
#include <cstdint>

#define NC 16
#define HWSZ (512*512)
#define NPIX (4*HWSZ)
#define TILE 128
#define NTILES (NPIX/TILE)      // 16384
#define GRID (148*4)            // 4 CTAs per SM

// ---------------- mma helpers ----------------------------------------------
__device__ __forceinline__ uint32_t sptr(const void* p) {
    return (uint32_t)__cvta_generic_to_shared(p);
}
__device__ __forceinline__ void ldm4(uint32_t& r0, uint32_t& r1, uint32_t& r2, uint32_t& r3,
                                     uint32_t addr) {
    asm volatile("ldmatrix.sync.aligned.m8n8.x4.shared.b16 {%0,%1,%2,%3}, [%4];"
                 : "=r"(r0), "=r"(r1), "=r"(r2), "=r"(r3) : "r"(addr));
}
__device__ __forceinline__ void mma16816(float* c, const uint32_t* a, uint32_t b0, uint32_t b1) {
    asm volatile("mma.sync.aligned.m16n8k16.row.col.f32.bf16.bf16.f32 "
                 "{%0,%1,%2,%3}, {%4,%5,%6,%7}, {%8,%9}, {%0,%1,%2,%3};"
                 : "+f"(c[0]), "+f"(c[1]), "+f"(c[2]), "+f"(c[3])
                 : "r"(a[0]), "r"(a[1]), "r"(a[2]), "r"(a[3]), "r"(b0), "r"(b1));
}
__device__ __forceinline__ uint32_t pack2(float a, float b) {
    __nv_bfloat162 h = __floats2bfloat162_rn(a, b);
    return *reinterpret_cast<uint32_t*>(&h);
}
__device__ __forceinline__ uint32_t packrelu2(float a, float b) {
    return pack2(fmaxf(a, 0.0f), fmaxf(b, 0.0f));
}
__device__ __forceinline__ float wred(float s) {
    #pragma unroll
    for (int d = 16; d > 0; d >>= 1) s += __shfl_xor_sync(0xffffffffu, s, d);
    return s;
}

// ---------------- single fused kernel --------------------------------------
__global__ __launch_bounds__(256)
void fused_kernel(const float* __restrict__ logits, float* __restrict__ out,
                  const float* __restrict__ E,
                  const float* __restrict__ aw1, const float* __restrict__ ab1,
                  const float* __restrict__ aw2, const float* __restrict__ ab2,
                  const float* __restrict__ w0,  const float* __restrict__ b0,
                  const float* __restrict__ w1,  const float* __restrict__ b1,
                  const float* __restrict__ fw,  const float* __restrict__ fb,
                  const float* __restrict__ ow,  const float* __restrict__ ob,
                  const float* __restrict__ gatep) {
    // Union region: prologue {Es 8K | ows 8K | e12 8K} vs main {Ls[2][16][136] 17.4K}
    __shared__ __align__(16) char Ubuf[24576];
    __shared__ float adjs[16][16];
    __shared__ float rs[16];
    __shared__ float c1s[128], c2s[16];
    __shared__ __align__(16) __nv_bfloat16 W1s[128][40];
    __shared__ __align__(16) __nv_bfloat16 W2s[16][152];
    // total static: 24576+1024+64+512+64+10240+4864 = 41344 B < 48K ; 4 CTA/SM = 165K < 228K

    float (*Es)[128]   = reinterpret_cast<float(*)[128]>(Ubuf);
    float (*ows)[128]  = reinterpret_cast<float(*)[128]>(Ubuf + 8192);
    float* e12p        = reinterpret_cast<float*>(Ubuf + 16384);        // [2][16][64]
    float (*Maggs)[16] = reinterpret_cast<float(*)[16]>(Ubuf + 16384);  // alias after adj
    float (*Ls)[16][136] = reinterpret_cast<float(*)[16][136]>(Ubuf);   // main phase [2][16][136]

    const int tid = threadIdx.x;
    const int lane = tid & 31;
    const int w = tid >> 5;
    const int t = lane & 3;
    const int g = lane >> 2;

    // ======================= PROLOGUE: weight folds ========================
    for (int i = tid; i < 512; i += 256) {
        reinterpret_cast<float4*>(Es)[i]  = reinterpret_cast<const float4*>(E)[i];
        reinterpret_cast<float4*>(ows)[i] = reinterpret_cast<const float4*>(ow)[i];
    }
    const float gate = *gatep;
    __syncthreads();

    // e1/e2 = relu(E @ aw^T + ab): 2048 outputs, warp-reduce
    for (int r = 0; r < 256; r++) {
        const int o = w * 256 + r;
        const int which = o >> 10, i = (o >> 6) & 15, k = o & 63;
        const float* __restrict__ awp = which ? aw2 : aw1;
        const float4 ev = *reinterpret_cast<const float4*>(&Es[i][4 * lane]);
        const float4 wv = *reinterpret_cast<const float4*>(&awp[k * 128 + 4 * lane]);
        const float s = wred(ev.x * wv.x + ev.y * wv.y + ev.z * wv.z + ev.w * wv.w);
        if (lane == 0) {
            const float v = fmaxf(s + (which ? ab2 : ab1)[k], 0.0f);
            e12p[which * 1024 + i * 64 + k] = v;
        }
    }
    __syncthreads();

    // adj = sigmoid(e1 @ e2^T) + I
    {
        const int i = tid >> 4, j = tid & 15;
        float s0 = 0.f, s1 = 0.f, s2 = 0.f, s3 = 0.f;
        #pragma unroll
        for (int k = 0; k < 64; k += 4) {
            s0 += e12p[i * 64 + k]     * e12p[1024 + j * 64 + k];
            s1 += e12p[i * 64 + k + 1] * e12p[1024 + j * 64 + k + 1];
            s2 += e12p[i * 64 + k + 2] * e12p[1024 + j * 64 + k + 2];
            s3 += e12p[i * 64 + k + 3] * e12p[1024 + j * 64 + k + 3];
        }
        const float s = (s0 + s1) + (s2 + s3);
        adjs[i][j] = 1.0f / (1.0f + expf(-s)) + ((i == j) ? 1.0f : 0.0f);
    }
    __syncthreads();
    if (tid < 16) {
        float s = 0.0f;
        #pragma unroll
        for (int j = 0; j < 16; j++) s += adjs[tid][j];
        rs[tid] = 1.0f / s;
    }
    __syncthreads();          // e12 reads done -> safe to overwrite as Maggs

    // Magg = (adj_norm @ E)^T -> Maggs (alias of e12) + W1s cols 16..31
    for (int idx = tid; idx < 2048; idx += 256) {
        const int c = idx >> 7, j = idx & 127;
        float s = 0.0f;
        #pragma unroll
        for (int i = 0; i < 16; i++) s += adjs[c][i] * Es[i][j];
        s *= rs[c];
        Maggs[j][c] = s;
        W1s[j][16 + c] = __float2bfloat16(s);
    }
    // A = W0 @ feat_w -> W1s cols 0..15
    for (int r = 0; r < 256; r++) {
        const int o = w * 256 + r;
        const int j = o >> 4, c = o & 15;
        const float4 wv = *reinterpret_cast<const float4*>(&w0[j * 128 + 4 * lane]);
        const float f0 = fw[(4 * lane)     * 16 + c];
        const float f1 = fw[(4 * lane + 1) * 16 + c];
        const float f2 = fw[(4 * lane + 2) * 16 + c];
        const float f3 = fw[(4 * lane + 3) * 16 + c];
        const float s = wred(wv.x * f0 + wv.y * f1 + wv.z * f2 + wv.w * f3);
        if (lane == 0) W1s[j][c] = __float2bfloat16(s);
    }
    // Bw = out_w @ W1 -> W2s cols 0..127
    {
        float a0 = 0.f, a1 = 0.f, a2 = 0.f, a3 = 0.f;
        float d0 = 0.f, d1 = 0.f, d2 = 0.f, d3 = 0.f;
        const int n0 = w, n1 = w + 8;
        for (int j = 0; j < 128; j++) {
            const float4 wv = *reinterpret_cast<const float4*>(&w1[j * 128 + 4 * lane]);
            const float oa = ows[n0][j], obv = ows[n1][j];
            a0 += oa * wv.x; a1 += oa * wv.y; a2 += oa * wv.z; a3 += oa * wv.w;
            d0 += obv * wv.x; d1 += obv * wv.y; d2 += obv * wv.z; d3 += obv * wv.w;
        }
        W2s[n0][4 * lane]     = __float2bfloat16(a0);
        W2s[n0][4 * lane + 1] = __float2bfloat16(a1);
        W2s[n0][4 * lane + 2] = __float2bfloat16(a2);
        W2s[n0][4 * lane + 3] = __float2bfloat16(a3);
        W2s[n1][4 * lane]     = __float2bfloat16(d0);
        W2s[n1][4 * lane + 1] = __float2bfloat16(d1);
        W2s[n1][4 * lane + 2] = __float2bfloat16(d2);
        W2s[n1][4 * lane + 3] = __float2bfloat16(d3);
    }
    // c1 = W0 @ feat_b + b0
    for (int r = 0; r < 16; r++) {
        const int j = w * 16 + r;
        const float4 wv = *reinterpret_cast<const float4*>(&w0[j * 128 + 4 * lane]);
        const float4 fv = *reinterpret_cast<const float4*>(&fb[4 * lane]);
        const float s = wred(wv.x * fv.x + wv.y * fv.y + wv.z * fv.z + wv.w * fv.w);
        if (lane == 0) c1s[j] = s + b0[j];
    }
    // c2 = out_w @ b1 + out_b
    for (int r = 0; r < 2; r++) {
        const int n = w * 2 + r;
        const float4 ov = *reinterpret_cast<const float4*>(&ows[n][4 * lane]);
        const float4 bv = *reinterpret_cast<const float4*>(&b1[4 * lane]);
        const float s = wred(ov.x * bv.x + ov.y * bv.y + ov.z * bv.z + ov.w * bv.w);
        if (lane == 0) c2s[n] = s + ob[n];
    }
    __syncthreads();          // Maggs complete before S
    // S = out_w @ Magg -> W2s cols 128..143
    {
        const int n = tid >> 4, c = tid & 15;
        float s0 = 0.f, s1 = 0.f, s2 = 0.f, s3 = 0.f;
        #pragma unroll
        for (int j = 0; j < 128; j += 4) {
            s0 += ows[n][j]     * Maggs[j][c];
            s1 += ows[n][j + 1] * Maggs[j + 1][c];
            s2 += ows[n][j + 2] * Maggs[j + 2][c];
            s3 += ows[n][j + 3] * Maggs[j + 3][c];
        }
        W2s[n][128 + c] = __float2bfloat16((s0 + s1) + (s2 + s3));
    }
    __syncthreads();

    // ---- hoist weight fragments into registers (ldmatrix, once) ----
    const int brow16 = (lane & 7) + ((lane >= 16) ? 8 : 0);
    const int bcol8 = (lane & 8) ? 8 : 0;

    uint32_t fW1[8][8];
    #pragma unroll
    for (int ntp = 0; ntp < 8; ntp++) {
        ldm4(fW1[ntp][0], fW1[ntp][1], fW1[ntp][2], fW1[ntp][3],
             sptr(&W1s[16 * ntp + brow16][bcol8]));
        ldm4(fW1[ntp][4], fW1[ntp][5], fW1[ntp][6], fW1[ntp][7],
             sptr(&W1s[16 * ntp + brow16][16 + bcol8]));
    }
    uint32_t fW2[9][4];
    #pragma unroll
    for (int kb = 0; kb < 8; kb++)
        ldm4(fW2[kb][0], fW2[kb][1], fW2[kb][2], fW2[kb][3],
             sptr(&W2s[brow16][16 * kb + bcol8]));
    ldm4(fW2[8][0], fW2[8][1], fW2[8][2], fW2[8][3],
         sptr(&W2s[brow16][128 + bcol8]));

    __syncthreads();   // prologue region (Es/ows/e12) now dead -> reuse as Ls

    // ======================= MAIN LOOP =====================================
    // 8KB tile prefetch via cp.async: 2 x float4 per thread, fully coalesced
    auto prefetch = [&](int tl, int bsel) {
        const int P = tl * TILE;
        const float* __restrict__ src =
            logits + (size_t)(P >> 18) * (NC * HWSZ) + (P & (HWSZ - 1));
        #pragma unroll
        for (int r = 0; r < 2; r++) {
            const int idx = tid + 256 * r;      // 0..511
            const int c = idx >> 5, v = idx & 31;
            const uint32_t daddr = sptr(&Ls[bsel][c][4 * v]);
            const float* sp = src + (size_t)c * HWSZ + 4 * v;
            asm volatile("cp.async.cg.shared.global [%0], [%1], 16;" :: "r"(daddr), "l"(sp));
        }
        asm volatile("cp.async.commit_group;");
    };

    const int stride = gridDim.x;
    int tile = blockIdx.x;
    prefetch(tile, 0);
    int buf = 0;
    const int pb = 16 * w;    // warp's pixel base within tile

    for (; tile < NTILES; tile += stride) {
        int nxt = tile + stride;
        if (nxt >= NTILES) nxt = tile;
        prefetch(nxt, buf ^ 1);
        asm volatile("cp.async.wait_group 1;");
        __syncthreads();

        // ---- read this lane's 8 fragment elements from the fp32 tile ----
        float l[8];
        l[0] = Ls[buf][2 * t][pb + g];       l[1] = Ls[buf][2 * t + 1][pb + g];
        l[2] = Ls[buf][2 * t][pb + g + 8];   l[3] = Ls[buf][2 * t + 1][pb + g + 8];
        l[4] = Ls[buf][2 * t + 8][pb + g];   l[5] = Ls[buf][2 * t + 9][pb + g];
        l[6] = Ls[buf][2 * t + 8][pb + g + 8]; l[7] = Ls[buf][2 * t + 9][pb + g + 8];

        // ---- softmax over 16 classes (4-lane t-group shuffles) ----
        float mx = fmaxf(fmaxf(l[0], l[1]), fmaxf(l[4], l[5]));
        float my = fmaxf(fmaxf(l[2], l[3]), fmaxf(l[6], l[7]));
        mx = fmaxf(mx, __shfl_xor_sync(0xffffffffu, mx, 1));
        mx = fmaxf(mx, __shfl_xor_sync(0xffffffffu, mx, 2));
        my = fmaxf(my, __shfl_xor_sync(0xffffffffu, my, 1));
        my = fmaxf(my, __shfl_xor_sync(0xffffffffu, my, 2));
        const float p0 = __expf(l[0] - mx), p1 = __expf(l[1] - mx);
        const float p4 = __expf(l[4] - mx), p5 = __expf(l[5] - mx);
        const float q2 = __expf(l[2] - my), q3 = __expf(l[3] - my);
        const float q6 = __expf(l[6] - my), q7 = __expf(l[7] - my);
        float sx = (p0 + p1) + (p4 + p5);
        float sy = (q2 + q3) + (q6 + q7);
        sx += __shfl_xor_sync(0xffffffffu, sx, 1);
        sx += __shfl_xor_sync(0xffffffffu, sx, 2);
        sy += __shfl_xor_sync(0xffffffffu, sy, 1);
        sy += __shfl_xor_sync(0xffffffffu, sy, 2);
        const float ix = 1.0f / sx, iy = 1.0f / sy;

        // ---- build A fragments ----
        uint32_t aL[4], aP[4];
        aL[0] = pack2(l[0], l[1]); aL[1] = pack2(l[2], l[3]);
        aL[2] = pack2(l[4], l[5]); aL[3] = pack2(l[6], l[7]);
        aP[0] = pack2(p0 * ix, p1 * ix); aP[1] = pack2(q2 * iy, q3 * iy);
        aP[2] = pack2(p4 * ix, p5 * ix); aP[3] = pack2(q6 * iy, q7 * iy);

        // ---- GEMM1: U[16,128] = [l|p] @ W1 + c1 ----
        float acc[16][4];
        #pragma unroll
        for (int nt = 0; nt < 16; nt++) {
            const float bv0 = c1s[8 * nt + 2 * t];
            const float bv1 = c1s[8 * nt + 2 * t + 1];
            acc[nt][0] = bv0; acc[nt][1] = bv1; acc[nt][2] = bv0; acc[nt][3] = bv1;
        }
        #pragma unroll
        for (int ntp = 0; ntp < 8; ntp++) {
            mma16816(acc[2 * ntp],     aL, fW1[ntp][0], fW1[ntp][1]);
            mma16816(acc[2 * ntp + 1], aL, fW1[ntp][2], fW1[ntp][3]);
            mma16816(acc[2 * ntp],     aP, fW1[ntp][4], fW1[ntp][5]);
            mma16816(acc[2 * ntp + 1], aP, fW1[ntp][6], fW1[ntp][7]);
        }

        // ---- GEMM2: R[16,16] = relu(U) @ Bw^T + p @ S^T + c2 ----
        float racc[2][4];
        #pragma unroll
        for (int nt = 0; nt < 2; nt++) {
            const float bv0 = c2s[8 * nt + 2 * t];
            const float bv1 = c2s[8 * nt + 2 * t + 1];
            racc[nt][0] = bv0; racc[nt][1] = bv1; racc[nt][2] = bv0; racc[nt][3] = bv1;
        }
        #pragma unroll
        for (int kb = 0; kb < 8; kb++) {
            uint32_t h[4];
            h[0] = packrelu2(acc[2 * kb][0],     acc[2 * kb][1]);
            h[1] = packrelu2(acc[2 * kb][2],     acc[2 * kb][3]);
            h[2] = packrelu2(acc[2 * kb + 1][0], acc[2 * kb + 1][1]);
            h[3] = packrelu2(acc[2 * kb + 1][2], acc[2 * kb + 1][3]);
            mma16816(racc[0], h, fW2[kb][0], fW2[kb][1]);
            mma16816(racc[1], h, fW2[kb][2], fW2[kb][3]);
        }
        mma16816(racc[0], aP, fW2[8][0], fW2[8][1]);
        mma16816(racc[1], aP, fW2[8][2], fW2[8][3]);

        // ---- epilogue: gate*r + residual, write back into tile in-place ----
        Ls[buf][2 * t][pb + g]         = fmaf(gate, racc[0][0], l[0]);
        Ls[buf][2 * t + 1][pb + g]     = fmaf(gate, racc[0][1], l[1]);
        Ls[buf][2 * t][pb + g + 8]     = fmaf(gate, racc[0][2], l[2]);
        Ls[buf][2 * t + 1][pb + g + 8] = fmaf(gate, racc[0][3], l[3]);
        Ls[buf][2 * t + 8][pb + g]     = fmaf(gate, racc[1][0], l[4]);
        Ls[buf][2 * t + 9][pb + g]     = fmaf(gate, racc[1][1], l[5]);
        Ls[buf][2 * t + 8][pb + g + 8] = fmaf(gate, racc[1][2], l[6]);
        Ls[buf][2 * t + 9][pb + g + 8] = fmaf(gate, racc[1][3], l[7]);
        __syncthreads();

        // ---- coalesced float4 store of the whole tile ----
        {
            const int P = tile * TILE;
            float* __restrict__ dst =
                out + (size_t)(P >> 18) * (NC * HWSZ) + (P & (HWSZ - 1));
            #pragma unroll
            for (int r = 0; r < 2; r++) {
                const int idx = tid + 256 * r;
                const int c = idx >> 5, v = idx & 31;
                *reinterpret_cast<float4*>(dst + (size_t)c * HWSZ + 4 * v) =
                    *reinterpret_cast<const float4*>(&Ls[buf][c][4 * v]);
            }
        }
        __syncthreads();   // tile buffer free before next prefetch overwrites it
        buf ^= 1;
    }
}

// ---------------- launch -----------------------------------------------------
extern "C" void kernel_launch(void* const* d_in, const int* in_sizes, int n_in,
                              void* d_out, int out_size) {
    const float* logits = (const float*)d_in[0];
    const float* E      = (const float*)d_in[1];
    const float* aw1    = (const float*)d_in[2];
    const float* ab1    = (const float*)d_in[3];
    const float* aw2    = (const float*)d_in[4];
    const float* ab2    = (const float*)d_in[5];
    const float* w0     = (const float*)d_in[6];
    const float* b0     = (const float*)d_in[7];
    const float* w1     = (const float*)d_in[8];
    const float* b1     = (const float*)d_in[9];
    const float* fw     = (const float*)d_in[10];
    const float* fb     = (const float*)d_in[11];
    const float* ow     = (const float*)d_in[12];
    const float* ob     = (const float*)d_in[13];
    const float* gate   = (const float*)d_in[14];
    float* out = (float*)d_out;

    fused_kernel<<<GRID, 256>>>(logits, out, E, aw1, ab1, aw2, ab2,
                                w0, b0, w1, b1, fw, fb, ow, ob, gate);
}

// round 9
// speedup vs baseline: 6.0571x; 6.0571x over previous
#include <cuda_runtime.h>
#include <cuda_bf16.h>
#include <cstdint>

#define NC 16
#define HWSZ (512*512)
#define NPIX (4*HWSZ)
#define TILE 128
#define NTILES (NPIX/TILE)      // 16384
#define GRID 148

// ---------------- folded weights (device globals) ---------------------------
__device__ float g_c1[128];
__device__ float g_c2[16];
__device__ __nv_bfloat16 g_W1T[128 * 32];   // [j][k]: k<16 -> W0@fw ; k>=16 -> Magg
__device__ __nv_bfloat16 g_W2T[16 * 144];   // [n][k]: k<128 -> ow@W1 ; k>=128 -> ow@Magg

// ---------------- helpers ---------------------------------------------------
__device__ __forceinline__ uint32_t sptr(const void* p) {
    return (uint32_t)__cvta_generic_to_shared(p);
}
__device__ __forceinline__ void ldm4(uint32_t& r0, uint32_t& r1, uint32_t& r2, uint32_t& r3,
                                     uint32_t addr) {
    asm volatile("ldmatrix.sync.aligned.m8n8.x4.shared.b16 {%0,%1,%2,%3}, [%4];"
                 : "=r"(r0), "=r"(r1), "=r"(r2), "=r"(r3) : "r"(addr));
}
__device__ __forceinline__ void mma16816(float* c, const uint32_t* a, uint32_t b0, uint32_t b1) {
    asm volatile("mma.sync.aligned.m16n8k16.row.col.f32.bf16.bf16.f32 "
                 "{%0,%1,%2,%3}, {%4,%5,%6,%7}, {%8,%9}, {%0,%1,%2,%3};"
                 : "+f"(c[0]), "+f"(c[1]), "+f"(c[2]), "+f"(c[3])
                 : "r"(a[0]), "r"(a[1]), "r"(a[2]), "r"(a[3]), "r"(b0), "r"(b1));
}
__device__ __forceinline__ uint32_t pack2(float a, float b) {
    __nv_bfloat162 h = __floats2bfloat162_rn(a, b);
    return *reinterpret_cast<uint32_t*>(&h);
}
__device__ __forceinline__ uint32_t packrelu2(float a, float b) {
    return pack2(fmaxf(a, 0.0f), fmaxf(b, 0.0f));
}
__device__ __forceinline__ float wred(float s) {
    #pragma unroll
    for (int d = 16; d > 0; d >>= 1) s += __shfl_xor_sync(0xffffffffu, s, d);
    return s;
}

// ---------------- setup: ONE CTA, thread-per-output folds -------------------
__global__ __launch_bounds__(256)
void setup_kernel(const float* __restrict__ E,
                  const float* __restrict__ aw1, const float* __restrict__ ab1,
                  const float* __restrict__ aw2, const float* __restrict__ ab2,
                  const float* __restrict__ w0,  const float* __restrict__ b0,
                  const float* __restrict__ w1,  const float* __restrict__ b1,
                  const float* __restrict__ fw,  const float* __restrict__ fb,
                  const float* __restrict__ ow,  const float* __restrict__ ob) {
    __shared__ __align__(16) float Es[16][132];      // padded: 2-way max conflicts
    __shared__ __align__(16) float ows[16][128];
    __shared__ __align__(16) float fws[2048];        // fw linear [d*16+c]
    __shared__ float e12[2][16][64];
    __shared__ float adjs[16][16];
    __shared__ float rs[16];
    __shared__ float Maggs[128][16];

    const int tid = threadIdx.x;
    const int lane = tid & 31;
    const int w = tid >> 5;

    // stage small matrices
    for (int i = tid; i < 512; i += 256) {
        const float4 ev = reinterpret_cast<const float4*>(E)[i];
        const int r = i >> 5, c4 = (i & 31) * 4;
        *reinterpret_cast<float4*>(&Es[r][c4]) = ev;
        reinterpret_cast<float4*>(ows)[i] = reinterpret_cast<const float4*>(ow)[i];
        reinterpret_cast<float4*>(fws)[i] = reinterpret_cast<const float4*>(fw)[i];
    }
    __syncthreads();

    // e1/e2: thread-per-output; i = tid&15 (16 lanes share (which,k) -> aw broadcast)
    {
        const int i = tid & 15, kk = tid >> 4;       // kk 0..15
        for (int r = 0; r < 8; r++) {
            const int o = r * 16 + kk;               // 0..127
            const int which = o >> 6, k = o & 63;
            const float* __restrict__ awp = (which ? aw2 : aw1) + k * 128;
            float s0 = 0.f, s1 = 0.f, s2 = 0.f, s3 = 0.f;
            #pragma unroll 4
            for (int d = 0; d < 128; d += 4) {
                s0 += Es[i][d]     * awp[d];
                s1 += Es[i][d + 1] * awp[d + 1];
                s2 += Es[i][d + 2] * awp[d + 2];
                s3 += Es[i][d + 3] * awp[d + 3];
            }
            const float s = (s0 + s1) + (s2 + s3) + (which ? ab2 : ab1)[k];
            e12[which][i][k] = fmaxf(s, 0.0f);
        }
    }
    __syncthreads();

    // adj = sigmoid(e1 @ e2^T) + I
    {
        const int i = tid >> 4, j = tid & 15;
        float s0 = 0.f, s1 = 0.f, s2 = 0.f, s3 = 0.f;
        #pragma unroll 4
        for (int k = 0; k < 64; k += 4) {
            s0 += e12[0][i][k]     * e12[1][j][k];
            s1 += e12[0][i][k + 1] * e12[1][j][k + 1];
            s2 += e12[0][i][k + 2] * e12[1][j][k + 2];
            s3 += e12[0][i][k + 3] * e12[1][j][k + 3];
        }
        const float s = (s0 + s1) + (s2 + s3);
        adjs[i][j] = 1.0f / (1.0f + expf(-s)) + ((i == j) ? 1.0f : 0.0f);
    }
    __syncthreads();
    if (tid < 16) {
        float s = 0.0f;
        #pragma unroll
        for (int j = 0; j < 16; j++) s += adjs[tid][j];
        rs[tid] = 1.0f / s;
    }
    __syncthreads();

    // Magg -> Maggs + g_W1T cols 16..31 (16 lanes share j -> Es broadcast)
    for (int r = 0; r < 8; r++) {
        const int idx = r * 256 + tid;
        const int c = idx & 15, j = idx >> 4;
        float s = 0.0f;
        #pragma unroll
        for (int i = 0; i < 16; i++) s += adjs[c][i] * Es[i][j];
        s *= rs[c];
        Maggs[j][c] = s;
        g_W1T[j * 32 + 16 + c] = __float2bfloat16(s);
    }
    // A = W0 @ fw -> g_W1T cols 0..15 (16 lanes share j -> w0 row broadcast)
    for (int r = 0; r < 8; r++) {
        const int idx = r * 256 + tid;
        const int c = idx & 15, j = idx >> 4;
        const float* __restrict__ wr = w0 + j * 128;
        float s0 = 0.f, s1 = 0.f, s2 = 0.f, s3 = 0.f;
        #pragma unroll 4
        for (int d = 0; d < 128; d += 4) {
            s0 += wr[d]     * fws[d * 16 + c];
            s1 += wr[d + 1] * fws[(d + 1) * 16 + c];
            s2 += wr[d + 2] * fws[(d + 2) * 16 + c];
            s3 += wr[d + 3] * fws[(d + 3) * 16 + c];
        }
        g_W1T[j * 32 + c] = __float2bfloat16((s0 + s1) + (s2 + s3));
    }
    // Bw = ow @ W1 -> g_W2T cols 0..127; d = tid&127 coalesced, 8 n's reuse each w1 row
    {
        const int d = tid & 127, half = tid >> 7;    // n = half*8 + nn
        float acc[8] = {0, 0, 0, 0, 0, 0, 0, 0};
        for (int j = 0; j < 128; j++) {
            const float wv = w1[j * 128 + d];
            #pragma unroll
            for (int nn = 0; nn < 8; nn++) acc[nn] += ows[half * 8 + nn][j] * wv;
        }
        #pragma unroll
        for (int nn = 0; nn < 8; nn++)
            g_W2T[(half * 8 + nn) * 144 + d] = __float2bfloat16(acc[nn]);
    }
    // S = ow @ Magg -> g_W2T cols 128..143
    {
        const int n = tid >> 4, c = tid & 15;
        float s0 = 0.f, s1 = 0.f, s2 = 0.f, s3 = 0.f;
        #pragma unroll 4
        for (int j = 0; j < 128; j += 4) {
            s0 += ows[n][j]     * Maggs[j][c];
            s1 += ows[n][j + 1] * Maggs[j + 1][c];
            s2 += ows[n][j + 2] * Maggs[j + 2][c];
            s3 += ows[n][j + 3] * Maggs[j + 3][c];
        }
        g_W2T[n * 144 + 128 + c] = __float2bfloat16((s0 + s1) + (s2 + s3));
    }
    // c1 = W0 @ fb + b0 (warp-reduce, 16 per warp; w0 rows coalesced)
    for (int r = 0; r < 16; r++) {
        const int j = w * 16 + r;
        const float4 wv = *reinterpret_cast<const float4*>(&w0[j * 128 + 4 * lane]);
        const float4 fv = *reinterpret_cast<const float4*>(&fb[4 * lane]);
        const float s = wred(wv.x * fv.x + wv.y * fv.y + wv.z * fv.z + wv.w * fv.w);
        if (lane == 0) g_c1[j] = s + b0[j];
    }
    // c2 = ow @ b1 + ob (2 per warp)
    for (int r = 0; r < 2; r++) {
        const int n = w * 2 + r;
        const float4 ov = *reinterpret_cast<const float4*>(&ows[n][4 * lane]);
        const float4 bv = *reinterpret_cast<const float4*>(&b1[4 * lane]);
        const float s = wred(ov.x * bv.x + ov.y * bv.y + ov.z * bv.z + ov.w * bv.w);
        if (lane == 0) g_c2[n] = s + ob[n];
    }
}

// ---------------- refine: persistent CTAs, 3-deep cp.async pipeline ---------
__global__ __launch_bounds__(256)
void refine_kernel(const float* __restrict__ logits, float* __restrict__ out,
                   const float* __restrict__ gatep) {
    __shared__ __align__(16) float Ls[3][16][132];   // triple-buffered, conflict-free stride
    __shared__ __align__(16) __nv_bfloat16 W1s[128][40];
    __shared__ __align__(16) __nv_bfloat16 W2s[16][152];
    __shared__ float c1s[128], c2s[16];
    // static smem: 25344 + 10240 + 4864 + 576 = 41024 B < 48K

    const int tid = threadIdx.x;
    const int lane = tid & 31;
    const int w = tid >> 5;
    const int t = lane & 3;
    const int g = lane >> 2;

    // stage folded weights, hoist fragments
    for (int i = tid; i < 128 * 32; i += 256) W1s[i >> 5][i & 31] = g_W1T[i];
    for (int i = tid; i < 16 * 144; i += 256) W2s[i / 144][i % 144] = g_W2T[i];
    if (tid < 128) c1s[tid] = g_c1[tid];
    if (tid < 16)  c2s[tid] = g_c2[tid];
    const float gate = *gatep;
    __syncthreads();

    const int brow16 = (lane & 7) + ((lane >= 16) ? 8 : 0);
    const int bcol8 = (lane & 8) ? 8 : 0;
    uint32_t fW1[8][8];
    #pragma unroll
    for (int ntp = 0; ntp < 8; ntp++) {
        ldm4(fW1[ntp][0], fW1[ntp][1], fW1[ntp][2], fW1[ntp][3],
             sptr(&W1s[16 * ntp + brow16][bcol8]));
        ldm4(fW1[ntp][4], fW1[ntp][5], fW1[ntp][6], fW1[ntp][7],
             sptr(&W1s[16 * ntp + brow16][16 + bcol8]));
    }
    uint32_t fW2[9][4];
    #pragma unroll
    for (int kb = 0; kb < 8; kb++)
        ldm4(fW2[kb][0], fW2[kb][1], fW2[kb][2], fW2[kb][3],
             sptr(&W2s[brow16][16 * kb + bcol8]));
    ldm4(fW2[8][0], fW2[8][1], fW2[8][2], fW2[8][3],
         sptr(&W2s[brow16][128 + bcol8]));

    auto prefetch = [&](int tl, int bsel) {
        const int P = tl * TILE;
        const float* __restrict__ src =
            logits + (size_t)(P >> 18) * (NC * HWSZ) + (P & (HWSZ - 1));
        #pragma unroll
        for (int r = 0; r < 2; r++) {
            const int idx = tid + 256 * r;      // 0..511
            const int c = idx >> 5, v = idx & 31;
            const uint32_t daddr = sptr(&Ls[bsel][c][4 * v]);
            const float* sp = src + (size_t)c * HWSZ + 4 * v;
            asm volatile("cp.async.cg.shared.global [%0], [%1], 16;" :: "r"(daddr), "l"(sp));
        }
        asm volatile("cp.async.commit_group;");
    };

    const int stride = gridDim.x;
    int tile = blockIdx.x;
    prefetch(tile, 0);
    {
        int t1 = tile + stride; if (t1 >= NTILES) t1 = tile;
        prefetch(t1, 1);
    }
    int cb = 0;
    const int pb = 16 * w;

    for (; tile < NTILES; tile += stride) {
        int n2 = tile + 2 * stride; if (n2 >= NTILES) n2 = tile;
        int nb = cb + 2; if (nb >= 3) nb -= 3;
        prefetch(n2, nb);
        asm volatile("cp.async.wait_group 2;");
        __syncthreads();

        // ---- lane's 8 fragment elements (conflict-free: banks 8t+g) ----
        float l[8];
        l[0] = Ls[cb][2 * t][pb + g];         l[1] = Ls[cb][2 * t + 1][pb + g];
        l[2] = Ls[cb][2 * t][pb + g + 8];     l[3] = Ls[cb][2 * t + 1][pb + g + 8];
        l[4] = Ls[cb][2 * t + 8][pb + g];     l[5] = Ls[cb][2 * t + 9][pb + g];
        l[6] = Ls[cb][2 * t + 8][pb + g + 8]; l[7] = Ls[cb][2 * t + 9][pb + g + 8];

        // ---- softmax via 4-lane t-group shuffles ----
        float mx = fmaxf(fmaxf(l[0], l[1]), fmaxf(l[4], l[5]));
        float my = fmaxf(fmaxf(l[2], l[3]), fmaxf(l[6], l[7]));
        mx = fmaxf(mx, __shfl_xor_sync(0xffffffffu, mx, 1));
        mx = fmaxf(mx, __shfl_xor_sync(0xffffffffu, mx, 2));
        my = fmaxf(my, __shfl_xor_sync(0xffffffffu, my, 1));
        my = fmaxf(my, __shfl_xor_sync(0xffffffffu, my, 2));
        const float p0 = __expf(l[0] - mx), p1 = __expf(l[1] - mx);
        const float p4 = __expf(l[4] - mx), p5 = __expf(l[5] - mx);
        const float q2 = __expf(l[2] - my), q3 = __expf(l[3] - my);
        const float q6 = __expf(l[6] - my), q7 = __expf(l[7] - my);
        float sx = (p0 + p1) + (p4 + p5);
        float sy = (q2 + q3) + (q6 + q7);
        sx += __shfl_xor_sync(0xffffffffu, sx, 1);
        sx += __shfl_xor_sync(0xffffffffu, sx, 2);
        sy += __shfl_xor_sync(0xffffffffu, sy, 1);
        sy += __shfl_xor_sync(0xffffffffu, sy, 2);
        const float ix = 1.0f / sx, iy = 1.0f / sy;

        uint32_t aL[4], aP[4];
        aL[0] = pack2(l[0], l[1]); aL[1] = pack2(l[2], l[3]);
        aL[2] = pack2(l[4], l[5]); aL[3] = pack2(l[6], l[7]);
        aP[0] = pack2(p0 * ix, p1 * ix); aP[1] = pack2(q2 * iy, q3 * iy);
        aP[2] = pack2(p4 * ix, p5 * ix); aP[3] = pack2(q6 * iy, q7 * iy);

        // ---- GEMM1 ----
        float acc[16][4];
        #pragma unroll
        for (int nt = 0; nt < 16; nt++) {
            const float bv0 = c1s[8 * nt + 2 * t];
            const float bv1 = c1s[8 * nt + 2 * t + 1];
            acc[nt][0] = bv0; acc[nt][1] = bv1; acc[nt][2] = bv0; acc[nt][3] = bv1;
        }
        #pragma unroll
        for (int ntp = 0; ntp < 8; ntp++) {
            mma16816(acc[2 * ntp],     aL, fW1[ntp][0], fW1[ntp][1]);
            mma16816(acc[2 * ntp + 1], aL, fW1[ntp][2], fW1[ntp][3]);
            mma16816(acc[2 * ntp],     aP, fW1[ntp][4], fW1[ntp][5]);
            mma16816(acc[2 * ntp + 1], aP, fW1[ntp][6], fW1[ntp][7]);
        }

        // ---- GEMM2 ----
        float racc[2][4];
        #pragma unroll
        for (int nt = 0; nt < 2; nt++) {
            const float bv0 = c2s[8 * nt + 2 * t];
            const float bv1 = c2s[8 * nt + 2 * t + 1];
            racc[nt][0] = bv0; racc[nt][1] = bv1; racc[nt][2] = bv0; racc[nt][3] = bv1;
        }
        #pragma unroll
        for (int kb = 0; kb < 8; kb++) {
            uint32_t h[4];
            h[0] = packrelu2(acc[2 * kb][0],     acc[2 * kb][1]);
            h[1] = packrelu2(acc[2 * kb][2],     acc[2 * kb][3]);
            h[2] = packrelu2(acc[2 * kb + 1][0], acc[2 * kb + 1][1]);
            h[3] = packrelu2(acc[2 * kb + 1][2], acc[2 * kb + 1][3]);
            mma16816(racc[0], h, fW2[kb][0], fW2[kb][1]);
            mma16816(racc[1], h, fW2[kb][2], fW2[kb][3]);
        }
        mma16816(racc[0], aP, fW2[8][0], fW2[8][1]);
        mma16816(racc[1], aP, fW2[8][2], fW2[8][3]);

        // ---- epilogue into smem (conflict-free), then coalesced store ----
        Ls[cb][2 * t][pb + g]         = fmaf(gate, racc[0][0], l[0]);
        Ls[cb][2 * t + 1][pb + g]     = fmaf(gate, racc[0][1], l[1]);
        Ls[cb][2 * t][pb + g + 8]     = fmaf(gate, racc[0][2], l[2]);
        Ls[cb][2 * t + 1][pb + g + 8] = fmaf(gate, racc[0][3], l[3]);
        Ls[cb][2 * t + 8][pb + g]     = fmaf(gate, racc[1][0], l[4]);
        Ls[cb][2 * t + 9][pb + g]     = fmaf(gate, racc[1][1], l[5]);
        Ls[cb][2 * t + 8][pb + g + 8] = fmaf(gate, racc[1][2], l[6]);
        Ls[cb][2 * t + 9][pb + g + 8] = fmaf(gate, racc[1][3], l[7]);
        __syncthreads();

        {
            const int P = tile * TILE;
            float* __restrict__ dst =
                out + (size_t)(P >> 18) * (NC * HWSZ) + (P & (HWSZ - 1));
            #pragma unroll
            for (int r = 0; r < 2; r++) {
                const int idx = tid + 256 * r;
                const int c = idx >> 5, v = idx & 31;
                *reinterpret_cast<float4*>(dst + (size_t)c * HWSZ + 4 * v) =
                    *reinterpret_cast<const float4*>(&Ls[cb][c][4 * v]);
            }
        }
        __syncthreads();      // buffer free before it is prefetch-overwritten
        cb = cb + 1; if (cb >= 3) cb = 0;
    }
}

// ---------------- launch -----------------------------------------------------
extern "C" void kernel_launch(void* const* d_in, const int* in_sizes, int n_in,
                              void* d_out, int out_size) {
    const float* logits = (const float*)d_in[0];
    const float* E      = (const float*)d_in[1];
    const float* aw1    = (const float*)d_in[2];
    const float* ab1    = (const float*)d_in[3];
    const float* aw2    = (const float*)d_in[4];
    const float* ab2    = (const float*)d_in[5];
    const float* w0     = (const float*)d_in[6];
    const float* b0     = (const float*)d_in[7];
    const float* w1     = (const float*)d_in[8];
    const float* b1     = (const float*)d_in[9];
    const float* fw     = (const float*)d_in[10];
    const float* fb     = (const float*)d_in[11];
    const float* ow     = (const float*)d_in[12];
    const float* ob     = (const float*)d_in[13];
    const float* gate   = (const float*)d_in[14];
    float* out = (float*)d_out;

    setup_kernel<<<1, 256>>>(E, aw1, ab1, aw2, ab2, w0, b0, w1, b1, fw, fb, ow, ob);
    refine_kernel<<<GRID, 256>>>(logits, out, gate);
}

// round 10
// speedup vs baseline: 9.6584x; 1.5945x over previous
#include <cuda_runtime.h>
#include <cuda_bf16.h>
#include <cstdint>

#define NC 16
#define HWSZ (512*512)
#define NPIX (4*HWSZ)
#define TILE 128
#define NTILES (NPIX/TILE)      // 16384
#define GRID 148

// ---------------- folded weights (device globals) ---------------------------
__device__ float g_e1[16 * 64];
__device__ float g_e2[16 * 64];
__device__ float g_c1[128];
__device__ float g_c2[16];
__device__ __nv_bfloat16 g_W1T[128 * 32];   // [j][k]: k<16 -> W0@fw ; k>=16 -> Magg
__device__ __nv_bfloat16 g_W2T[16 * 144];   // [n][k]: k<128 -> ow@W1 ; k>=128 -> ow@Magg

// ---------------- helpers ---------------------------------------------------
__device__ __forceinline__ uint32_t sptr(const void* p) {
    return (uint32_t)__cvta_generic_to_shared(p);
}
__device__ __forceinline__ void ldm4(uint32_t& r0, uint32_t& r1, uint32_t& r2, uint32_t& r3,
                                     uint32_t addr) {
    asm volatile("ldmatrix.sync.aligned.m8n8.x4.shared.b16 {%0,%1,%2,%3}, [%4];"
                 : "=r"(r0), "=r"(r1), "=r"(r2), "=r"(r3) : "r"(addr));
}
__device__ __forceinline__ void mma16816(float* c, const uint32_t* a, uint32_t b0, uint32_t b1) {
    asm volatile("mma.sync.aligned.m16n8k16.row.col.f32.bf16.bf16.f32 "
                 "{%0,%1,%2,%3}, {%4,%5,%6,%7}, {%8,%9}, {%0,%1,%2,%3};"
                 : "+f"(c[0]), "+f"(c[1]), "+f"(c[2]), "+f"(c[3])
                 : "r"(a[0]), "r"(a[1]), "r"(a[2]), "r"(a[3]), "r"(b0), "r"(b1));
}
__device__ __forceinline__ uint32_t pack2(float a, float b) {
    __nv_bfloat162 h = __floats2bfloat162_rn(a, b);
    return *reinterpret_cast<uint32_t*>(&h);
}
__device__ __forceinline__ uint32_t packrelu2(float a, float b) {
    return pack2(fmaxf(a, 0.0f), fmaxf(b, 0.0f));
}
__device__ __forceinline__ float wred(float s) {
    #pragma unroll
    for (int d = 16; d > 0; d >>= 1) s += __shfl_xor_sync(0xffffffffu, s, d);
    return s;
}

// ---------------- setup_x: parallel folds (33 CTAs) -------------------------
__global__ __launch_bounds__(256)
void setup_x(const float* __restrict__ E,
             const float* __restrict__ aw1, const float* __restrict__ ab1,
             const float* __restrict__ aw2, const float* __restrict__ ab2,
             const float* __restrict__ w0,  const float* __restrict__ b0,
             const float* __restrict__ w1,  const float* __restrict__ b1,
             const float* __restrict__ fw,  const float* __restrict__ fb,
             const float* __restrict__ ow,  const float* __restrict__ ob) {
    const int tid = threadIdx.x;
    const int blk = blockIdx.x;
    if (blk < 16) {
        // e1/e2: warp-per-output (proven fast in round 4)
        const int lane = tid & 31;
        const int warp = (blk << 3) | (tid >> 5);   // 0..127
        for (int r = 0; r < 16; r++) {
            const int o = warp * 16 + r;
            const int which = o >> 10;
            const int i = (o >> 6) & 15;
            const int k = o & 63;
            const float* __restrict__ wp = which ? aw2 : aw1;
            const float4 ev = *reinterpret_cast<const float4*>(E + i * 128 + 4 * lane);
            const float4 wv = *reinterpret_cast<const float4*>(wp + k * 128 + 4 * lane);
            const float s = wred(ev.x * wv.x + ev.y * wv.y + ev.z * wv.z + ev.w * wv.w);
            if (lane == 0) {
                const float v = fmaxf(s + (which ? ab2 : ab1)[k], 0.0f);
                if (which) g_e2[i * 64 + k] = v; else g_e1[i * 64 + k] = v;
            }
        }
    } else if (blk < 24) {
        // Bw = ow @ W1 -> g_W2T cols 0..127 (d fast -> coalesced w1 reads)
        const int idx = (blk - 16) * 256 + tid;
        const int n = idx >> 7, d = idx & 127;
        float s0 = 0.f, s1 = 0.f, s2 = 0.f, s3 = 0.f;
        #pragma unroll 4
        for (int j = 0; j < 128; j += 4) {
            s0 += ow[n * 128 + j]     * w1[(j)     * 128 + d];
            s1 += ow[n * 128 + j + 1] * w1[(j + 1) * 128 + d];
            s2 += ow[n * 128 + j + 2] * w1[(j + 2) * 128 + d];
            s3 += ow[n * 128 + j + 3] * w1[(j + 3) * 128 + d];
        }
        g_W2T[n * 144 + d] = __float2bfloat16((s0 + s1) + (s2 + s3));
    } else if (blk < 32) {
        // A = W0 @ fw -> g_W1T cols 0..15 (c fast -> coalesced fw reads)
        const int idx = (blk - 24) * 256 + tid;
        const int j = idx >> 4, c = idx & 15;
        float s0 = 0.f, s1 = 0.f, s2 = 0.f, s3 = 0.f;
        #pragma unroll 4
        for (int d = 0; d < 128; d += 4) {
            s0 += w0[j * 128 + d]     * fw[(d)     * 16 + c];
            s1 += w0[j * 128 + d + 1] * fw[(d + 1) * 16 + c];
            s2 += w0[j * 128 + d + 2] * fw[(d + 2) * 16 + c];
            s3 += w0[j * 128 + d + 3] * fw[(d + 3) * 16 + c];
        }
        g_W1T[j * 32 + c] = __float2bfloat16((s0 + s1) + (s2 + s3));
    } else {
        // c1, c2
        if (tid < 128) {
            float s0 = b0[tid], s1 = 0.f, s2 = 0.f, s3 = 0.f;
            #pragma unroll 4
            for (int d = 0; d < 128; d += 4) {
                s0 += w0[tid * 128 + d]     * fb[d];
                s1 += w0[tid * 128 + d + 1] * fb[d + 1];
                s2 += w0[tid * 128 + d + 2] * fb[d + 2];
                s3 += w0[tid * 128 + d + 3] * fb[d + 3];
            }
            g_c1[tid] = (s0 + s1) + (s2 + s3);
        }
        if (tid < 16) {
            float s0 = ob[tid], s1 = 0.f, s2 = 0.f, s3 = 0.f;
            #pragma unroll 4
            for (int j = 0; j < 128; j += 4) {
                s0 += ow[tid * 128 + j]     * b1[j];
                s1 += ow[tid * 128 + j + 1] * b1[j + 1];
                s2 += ow[tid * 128 + j + 2] * b1[j + 2];
                s3 += ow[tid * 128 + j + 3] * b1[j + 3];
            }
            g_c2[tid] = (s0 + s1) + (s2 + s3);
        }
    }
}

// ---------------- setup_y: adjacency chain (1 tiny CTA) ---------------------
__global__ __launch_bounds__(256)
void setup_y(const float* __restrict__ E, const float* __restrict__ ow) {
    __shared__ float e1s[16][64];
    __shared__ float e2s[16][64];
    __shared__ float adjs[16][16];
    __shared__ float rs[16];
    __shared__ float Maggs[128][16];
    const int tid = threadIdx.x;

    for (int i = tid; i < 1024; i += 256) {
        e1s[i >> 6][i & 63] = g_e1[i];
        e2s[i >> 6][i & 63] = g_e2[i];
    }
    __syncthreads();
    {
        const int i = tid >> 4, j = tid & 15;
        float s0 = 0.f, s1 = 0.f, s2 = 0.f, s3 = 0.f;
        #pragma unroll 4
        for (int k = 0; k < 64; k += 4) {
            s0 += e1s[i][k]     * e2s[j][k];
            s1 += e1s[i][k + 1] * e2s[j][k + 1];
            s2 += e1s[i][k + 2] * e2s[j][k + 2];
            s3 += e1s[i][k + 3] * e2s[j][k + 3];
        }
        const float s = (s0 + s1) + (s2 + s3);
        adjs[i][j] = 1.0f / (1.0f + expf(-s)) + ((i == j) ? 1.0f : 0.0f);
    }
    __syncthreads();
    if (tid < 16) {
        float s = 0.0f;
        #pragma unroll
        for (int j = 0; j < 16; j++) s += adjs[tid][j];
        rs[tid] = 1.0f / s;
    }
    __syncthreads();
    // Magg -> Maggs + g_W1T cols 16..31 (j fast -> coalesced E reads)
    for (int idx = tid; idx < 2048; idx += 256) {
        const int c = idx >> 7, j = idx & 127;
        float s = 0.0f;
        #pragma unroll
        for (int i = 0; i < 16; i++) s += adjs[c][i] * E[i * 128 + j];
        s *= rs[c];
        Maggs[j][c] = s;
        g_W1T[j * 32 + 16 + c] = __float2bfloat16(s);
    }
    __syncthreads();
    // S = ow @ Magg -> g_W2T cols 128..143
    {
        const int n = tid >> 4, c = tid & 15;
        float s0 = 0.f, s1 = 0.f, s2 = 0.f, s3 = 0.f;
        #pragma unroll 4
        for (int j = 0; j < 128; j += 4) {
            s0 += ow[n * 128 + j]     * Maggs[j][c];
            s1 += ow[n * 128 + j + 1] * Maggs[j + 1][c];
            s2 += ow[n * 128 + j + 2] * Maggs[j + 2][c];
            s3 += ow[n * 128 + j + 3] * Maggs[j + 3][c];
        }
        g_W2T[n * 144 + 128 + c] = __float2bfloat16((s0 + s1) + (s2 + s3));
    }
}

// ---------------- refine: 2 CTAs/SM, interleaved GEMM1/GEMM2 ----------------
__global__ __launch_bounds__(256, 2)
void refine_kernel(const float* __restrict__ logits, float* __restrict__ out,
                   const float* __restrict__ gatep) {
    __shared__ __align__(16) float Ls[3][16][132];
    __shared__ __align__(16) __nv_bfloat16 W1s[128][40];
    __shared__ __align__(16) __nv_bfloat16 W2s[16][152];
    __shared__ float c1s[128], c2s[16];
    // static smem ~41KB/CTA -> 82KB/SM at 2 CTAs (fits)

    const int tid = threadIdx.x;
    const int lane = tid & 31;
    const int w = tid >> 5;
    const int t = lane & 3;
    const int g = lane >> 2;

    for (int i = tid; i < 128 * 32; i += 256) W1s[i >> 5][i & 31] = g_W1T[i];
    for (int i = tid; i < 16 * 144; i += 256) W2s[i / 144][i % 144] = g_W2T[i];
    if (tid < 128) c1s[tid] = g_c1[tid];
    if (tid < 16)  c2s[tid] = g_c2[tid];
    const float gate = *gatep;
    __syncthreads();

    const int brow16 = (lane & 7) + ((lane >= 16) ? 8 : 0);
    const int bcol8 = (lane & 8) ? 8 : 0;

    // register-resident: W1 fragments (64 regs) + S fragment (4 regs)
    uint32_t fW1[8][8];
    #pragma unroll
    for (int ntp = 0; ntp < 8; ntp++) {
        ldm4(fW1[ntp][0], fW1[ntp][1], fW1[ntp][2], fW1[ntp][3],
             sptr(&W1s[16 * ntp + brow16][bcol8]));
        ldm4(fW1[ntp][4], fW1[ntp][5], fW1[ntp][6], fW1[ntp][7],
             sptr(&W1s[16 * ntp + brow16][16 + bcol8]));
    }
    uint32_t fS[4];
    ldm4(fS[0], fS[1], fS[2], fS[3], sptr(&W2s[brow16][128 + bcol8]));
    const uint32_t w2base = sptr(&W2s[brow16][bcol8]);

    auto prefetch = [&](int tl, int bsel) {
        const int P = tl * TILE;
        const float* __restrict__ src =
            logits + (size_t)(P >> 18) * (NC * HWSZ) + (P & (HWSZ - 1));
        #pragma unroll
        for (int r = 0; r < 2; r++) {
            const int idx = tid + 256 * r;
            const int c = idx >> 5, v = idx & 31;
            const uint32_t daddr = sptr(&Ls[bsel][c][4 * v]);
            const float* sp = src + (size_t)c * HWSZ + 4 * v;
            asm volatile("cp.async.cg.shared.global [%0], [%1], 16;" :: "r"(daddr), "l"(sp));
        }
        asm volatile("cp.async.commit_group;");
    };

    const int stride = gridDim.x;
    int tile = blockIdx.x;
    prefetch(tile, 0);
    {
        int t1 = tile + stride; if (t1 >= NTILES) t1 = tile;
        prefetch(t1, 1);
    }
    int cb = 0;
    const int pb = 16 * w;

    for (; tile < NTILES; tile += stride) {
        int n2 = tile + 2 * stride; if (n2 >= NTILES) n2 = tile;
        int nb = cb + 2; if (nb >= 3) nb -= 3;
        prefetch(n2, nb);
        asm volatile("cp.async.wait_group 2;");
        __syncthreads();

        // ---- softmax + fragments (l values not kept live past packing) ----
        uint32_t aL[4], aP[4];
        {
            float l0 = Ls[cb][2 * t][pb + g],         l1 = Ls[cb][2 * t + 1][pb + g];
            float l2 = Ls[cb][2 * t][pb + g + 8],     l3 = Ls[cb][2 * t + 1][pb + g + 8];
            float l4 = Ls[cb][2 * t + 8][pb + g],     l5 = Ls[cb][2 * t + 9][pb + g];
            float l6 = Ls[cb][2 * t + 8][pb + g + 8], l7 = Ls[cb][2 * t + 9][pb + g + 8];
            float mx = fmaxf(fmaxf(l0, l1), fmaxf(l4, l5));
            float my = fmaxf(fmaxf(l2, l3), fmaxf(l6, l7));
            mx = fmaxf(mx, __shfl_xor_sync(0xffffffffu, mx, 1));
            mx = fmaxf(mx, __shfl_xor_sync(0xffffffffu, mx, 2));
            my = fmaxf(my, __shfl_xor_sync(0xffffffffu, my, 1));
            my = fmaxf(my, __shfl_xor_sync(0xffffffffu, my, 2));
            const float p0 = __expf(l0 - mx), p1 = __expf(l1 - mx);
            const float p4 = __expf(l4 - mx), p5 = __expf(l5 - mx);
            const float q2 = __expf(l2 - my), q3 = __expf(l3 - my);
            const float q6 = __expf(l6 - my), q7 = __expf(l7 - my);
            float sx = (p0 + p1) + (p4 + p5);
            float sy = (q2 + q3) + (q6 + q7);
            sx += __shfl_xor_sync(0xffffffffu, sx, 1);
            sx += __shfl_xor_sync(0xffffffffu, sx, 2);
            sy += __shfl_xor_sync(0xffffffffu, sy, 1);
            sy += __shfl_xor_sync(0xffffffffu, sy, 2);
            const float ix = 1.0f / sx, iy = 1.0f / sy;
            aL[0] = pack2(l0, l1); aL[1] = pack2(l2, l3);
            aL[2] = pack2(l4, l5); aL[3] = pack2(l6, l7);
            aP[0] = pack2(p0 * ix, p1 * ix); aP[1] = pack2(q2 * iy, q3 * iy);
            aP[2] = pack2(p4 * ix, p5 * ix); aP[3] = pack2(q6 * iy, q7 * iy);
        }

        // ---- interleaved GEMM1 -> relu -> GEMM2 (acc live range = 1 kb) ----
        float racc[2][4];
        #pragma unroll
        for (int nt = 0; nt < 2; nt++) {
            const float bv0 = c2s[8 * nt + 2 * t];
            const float bv1 = c2s[8 * nt + 2 * t + 1];
            racc[nt][0] = bv0; racc[nt][1] = bv1; racc[nt][2] = bv0; racc[nt][3] = bv1;
        }
        mma16816(racc[0], aP, fS[0], fS[1]);
        mma16816(racc[1], aP, fS[2], fS[3]);
        #pragma unroll
        for (int kb = 0; kb < 8; kb++) {
            uint32_t b0, b1, b2, b3;
            ldm4(b0, b1, b2, b3, w2base + 32 * kb);   // W2s row stride pre-baked in addr
            float acc0[4], acc1[4];
            {
                const float a00 = c1s[16 * kb + 2 * t];
                const float a01 = c1s[16 * kb + 2 * t + 1];
                const float a10 = c1s[16 * kb + 8 + 2 * t];
                const float a11 = c1s[16 * kb + 8 + 2 * t + 1];
                acc0[0] = a00; acc0[1] = a01; acc0[2] = a00; acc0[3] = a01;
                acc1[0] = a10; acc1[1] = a11; acc1[2] = a10; acc1[3] = a11;
            }
            mma16816(acc0, aL, fW1[kb][0], fW1[kb][1]);
            mma16816(acc1, aL, fW1[kb][2], fW1[kb][3]);
            mma16816(acc0, aP, fW1[kb][4], fW1[kb][5]);
            mma16816(acc1, aP, fW1[kb][6], fW1[kb][7]);
            uint32_t h[4];
            h[0] = packrelu2(acc0[0], acc0[1]);
            h[1] = packrelu2(acc0[2], acc0[3]);
            h[2] = packrelu2(acc1[0], acc1[1]);
            h[3] = packrelu2(acc1[2], acc1[3]);
            mma16816(racc[0], h, b0, b1);
            mma16816(racc[1], h, b2, b3);
        }

        // ---- epilogue: residual re-read from smem, write back, store ----
        Ls[cb][2 * t][pb + g]         = fmaf(gate, racc[0][0], Ls[cb][2 * t][pb + g]);
        Ls[cb][2 * t + 1][pb + g]     = fmaf(gate, racc[0][1], Ls[cb][2 * t + 1][pb + g]);
        Ls[cb][2 * t][pb + g + 8]     = fmaf(gate, racc[0][2], Ls[cb][2 * t][pb + g + 8]);
        Ls[cb][2 * t + 1][pb + g + 8] = fmaf(gate, racc[0][3], Ls[cb][2 * t + 1][pb + g + 8]);
        Ls[cb][2 * t + 8][pb + g]     = fmaf(gate, racc[1][0], Ls[cb][2 * t + 8][pb + g]);
        Ls[cb][2 * t + 9][pb + g]     = fmaf(gate, racc[1][1], Ls[cb][2 * t + 9][pb + g]);
        Ls[cb][2 * t + 8][pb + g + 8] = fmaf(gate, racc[1][2], Ls[cb][2 * t + 8][pb + g + 8]);
        Ls[cb][2 * t + 9][pb + g + 8] = fmaf(gate, racc[1][3], Ls[cb][2 * t + 9][pb + g + 8]);
        __syncthreads();

        {
            const int P = tile * TILE;
            float* __restrict__ dst =
                out + (size_t)(P >> 18) * (NC * HWSZ) + (P & (HWSZ - 1));
            #pragma unroll
            for (int r = 0; r < 2; r++) {
                const int idx = tid + 256 * r;
                const int c = idx >> 5, v = idx & 31;
                *reinterpret_cast<float4*>(dst + (size_t)c * HWSZ + 4 * v) =
                    *reinterpret_cast<const float4*>(&Ls[cb][c][4 * v]);
            }
        }
        __syncthreads();
        cb = cb + 1; if (cb >= 3) cb = 0;
    }
}

// ---------------- launch -----------------------------------------------------
extern "C" void kernel_launch(void* const* d_in, const int* in_sizes, int n_in,
                              void* d_out, int out_size) {
    const float* logits = (const float*)d_in[0];
    const float* E      = (const float*)d_in[1];
    const float* aw1    = (const float*)d_in[2];
    const float* ab1    = (const float*)d_in[3];
    const float* aw2    = (const float*)d_in[4];
    const float* ab2    = (const float*)d_in[5];
    const float* w0     = (const float*)d_in[6];
    const float* b0     = (const float*)d_in[7];
    const float* w1     = (const float*)d_in[8];
    const float* b1     = (const float*)d_in[9];
    const float* fw     = (const float*)d_in[10];
    const float* fb     = (const float*)d_in[11];
    const float* ow     = (const float*)d_in[12];
    const float* ob     = (const float*)d_in[13];
    const float* gate   = (const float*)d_in[14];
    float* out = (float*)d_out;

    setup_x<<<33, 256>>>(E, aw1, ab1, aw2, ab2, w0, b0, w1, b1, fw, fb, ow, ob);
    setup_y<<<1, 256>>>(E, ow);
    refine_kernel<<<GRID * 2, 256>>>(logits, out, gate);
}

// round 11
// speedup vs baseline: 12.5592x; 1.3003x over previous
#include <cuda_runtime.h>
#include <cuda_bf16.h>
#include <cstdint>

#define NC 16
#define HWSZ (512*512)
#define NPIX (4*HWSZ)
#define WT_TOTAL (NPIX/16)      // 65536 warp-tiles of 16 pixels
#define GRID 296                // 2 CTAs per SM
#define NW (GRID*8)             // 2368 warps total

// ---------------- folded weights (device globals) ---------------------------
__device__ float g_e1[16 * 64];
__device__ float g_e2[16 * 64];
__device__ float g_c1[128];
__device__ float g_c2[16];
__device__ __nv_bfloat16 g_W1T[128 * 32];   // [j][k]: k<16 -> W0@fw ; k>=16 -> Magg
__device__ __nv_bfloat16 g_W2T[16 * 144];   // [n][k]: k<128 -> ow@W1 ; k>=128 -> ow@Magg

// ---------------- helpers ---------------------------------------------------
__device__ __forceinline__ uint32_t sptr(const void* p) {
    return (uint32_t)__cvta_generic_to_shared(p);
}
__device__ __forceinline__ void ldm4(uint32_t& r0, uint32_t& r1, uint32_t& r2, uint32_t& r3,
                                     uint32_t addr) {
    asm volatile("ldmatrix.sync.aligned.m8n8.x4.shared.b16 {%0,%1,%2,%3}, [%4];"
                 : "=r"(r0), "=r"(r1), "=r"(r2), "=r"(r3) : "r"(addr));
}
__device__ __forceinline__ void mma16816(float* c, const uint32_t* a, uint32_t b0, uint32_t b1) {
    asm volatile("mma.sync.aligned.m16n8k16.row.col.f32.bf16.bf16.f32 "
                 "{%0,%1,%2,%3}, {%4,%5,%6,%7}, {%8,%9}, {%0,%1,%2,%3};"
                 : "+f"(c[0]), "+f"(c[1]), "+f"(c[2]), "+f"(c[3])
                 : "r"(a[0]), "r"(a[1]), "r"(a[2]), "r"(a[3]), "r"(b0), "r"(b1));
}
__device__ __forceinline__ uint32_t pack2(float a, float b) {
    __nv_bfloat162 h = __floats2bfloat162_rn(a, b);
    return *reinterpret_cast<uint32_t*>(&h);
}
__device__ __forceinline__ uint32_t packrelu2(float a, float b) {
    return pack2(fmaxf(a, 0.0f), fmaxf(b, 0.0f));
}
__device__ __forceinline__ float wred(float s) {
    #pragma unroll
    for (int d = 16; d > 0; d >>= 1) s += __shfl_xor_sync(0xffffffffu, s, d);
    return s;
}

// ---------------- setup_x: maximally parallel folds (337 CTAs) --------------
__global__ __launch_bounds__(256)
void setup_x(const float* __restrict__ E,
             const float* __restrict__ aw1, const float* __restrict__ ab1,
             const float* __restrict__ aw2, const float* __restrict__ ab2,
             const float* __restrict__ w0,  const float* __restrict__ b0,
             const float* __restrict__ w1,  const float* __restrict__ b1,
             const float* __restrict__ fw,  const float* __restrict__ fb,
             const float* __restrict__ ow,  const float* __restrict__ ob) {
    const int tid = threadIdx.x;
    const int lane = tid & 31;
    const int w = tid >> 5;
    const int blk = blockIdx.x;

    if (blk < 256) {
        // e1/e2: ONE output per warp
        const int wid = (blk << 3) | w;              // 0..2047
        const int which = wid >> 10, i = (wid >> 6) & 15, k = wid & 63;
        const float* __restrict__ wp = which ? aw2 : aw1;
        const float4 ev = *reinterpret_cast<const float4*>(E + i * 128 + 4 * lane);
        const float4 wv = *reinterpret_cast<const float4*>(wp + k * 128 + 4 * lane);
        const float s = wred(ev.x * wv.x + ev.y * wv.y + ev.z * wv.z + ev.w * wv.w);
        if (lane == 0) {
            const float v = fmaxf(s + (which ? ab2 : ab1)[k], 0.0f);
            if (which) g_e2[i * 64 + k] = v; else g_e1[i * 64 + k] = v;
        }
    } else if (blk < 288) {
        // Bw = ow @ W1: 4 threads per output (k split 4x32), shfl-pair reduce
        const int tg = (blk - 256) * 256 + tid;      // 0..8191
        const int o = tg >> 2, sub = tg & 3;
        const int n = o >> 7, d = o & 127;
        const float* __restrict__ owr = ow + n * 128 + sub * 32;
        float s0 = 0.f, s1 = 0.f;
        #pragma unroll 8
        for (int j = 0; j < 32; j += 2) {
            s0 += owr[j]     * w1[(sub * 32 + j)     * 128 + d];
            s1 += owr[j + 1] * w1[(sub * 32 + j + 1) * 128 + d];
        }
        float s = s0 + s1;
        s += __shfl_xor_sync(0xffffffffu, s, 1);
        s += __shfl_xor_sync(0xffffffffu, s, 2);
        if (sub == 0) g_W2T[n * 144 + d] = __float2bfloat16(s);
    } else if (blk < 320) {
        // A = W0 @ fw: 4 threads per output (d split 4x32)
        const int tg = (blk - 288) * 256 + tid;
        const int o = tg >> 2, sub = tg & 3;
        const int j = o >> 4, c = o & 15;
        const float* __restrict__ wr = w0 + j * 128 + sub * 32;
        float s0 = 0.f, s1 = 0.f;
        #pragma unroll 8
        for (int d = 0; d < 32; d += 2) {
            s0 += wr[d]     * fw[(sub * 32 + d)     * 16 + c];
            s1 += wr[d + 1] * fw[(sub * 32 + d + 1) * 16 + c];
        }
        float s = s0 + s1;
        s += __shfl_xor_sync(0xffffffffu, s, 1);
        s += __shfl_xor_sync(0xffffffffu, s, 2);
        if (sub == 0) g_W1T[j * 32 + c] = __float2bfloat16(s);
    } else if (blk < 336) {
        // c1: ONE output per warp (128 warps over 16 CTAs)
        const int j = ((blk - 320) << 3) | w;        // 0..127
        const float4 wv = *reinterpret_cast<const float4*>(&w0[j * 128 + 4 * lane]);
        const float4 fv = *reinterpret_cast<const float4*>(&fb[4 * lane]);
        const float s = wred(wv.x * fv.x + wv.y * fv.y + wv.z * fv.z + wv.w * fv.w);
        if (lane == 0) g_c1[j] = s + b0[j];
    } else {
        // c2: 2 outputs per warp
        for (int r = 0; r < 2; r++) {
            const int n = w * 2 + r;
            const float4 ov = *reinterpret_cast<const float4*>(&ow[n * 128 + 4 * lane]);
            const float4 bv = *reinterpret_cast<const float4*>(&b1[4 * lane]);
            const float s = wred(ov.x * bv.x + ov.y * bv.y + ov.z * bv.z + ov.w * bv.w);
            if (lane == 0) g_c2[n] = s + ob[n];
        }
    }
}

// ---------------- setup_y: adjacency chain (1 tiny CTA) ---------------------
__global__ __launch_bounds__(256)
void setup_y(const float* __restrict__ E, const float* __restrict__ ow) {
    __shared__ float e1s[16][64];
    __shared__ float e2s[16][64];
    __shared__ float adjs[16][16];
    __shared__ float rs[16];
    __shared__ float Maggs[128][16];
    const int tid = threadIdx.x;

    for (int i = tid; i < 1024; i += 256) {
        e1s[i >> 6][i & 63] = g_e1[i];
        e2s[i >> 6][i & 63] = g_e2[i];
    }
    __syncthreads();
    {
        const int i = tid >> 4, j = tid & 15;
        float s0 = 0.f, s1 = 0.f, s2 = 0.f, s3 = 0.f;
        #pragma unroll 4
        for (int k = 0; k < 64; k += 4) {
            s0 += e1s[i][k]     * e2s[j][k];
            s1 += e1s[i][k + 1] * e2s[j][k + 1];
            s2 += e1s[i][k + 2] * e2s[j][k + 2];
            s3 += e1s[i][k + 3] * e2s[j][k + 3];
        }
        const float s = (s0 + s1) + (s2 + s3);
        adjs[i][j] = 1.0f / (1.0f + expf(-s)) + ((i == j) ? 1.0f : 0.0f);
    }
    __syncthreads();
    if (tid < 16) {
        float s = 0.0f;
        #pragma unroll
        for (int j = 0; j < 16; j++) s += adjs[tid][j];
        rs[tid] = 1.0f / s;
    }
    __syncthreads();
    for (int idx = tid; idx < 2048; idx += 256) {
        const int c = idx >> 7, j = idx & 127;
        float s = 0.0f;
        #pragma unroll
        for (int i = 0; i < 16; i++) s += adjs[c][i] * E[i * 128 + j];
        s *= rs[c];
        Maggs[j][c] = s;
        g_W1T[j * 32 + 16 + c] = __float2bfloat16(s);
    }
    __syncthreads();
    {
        const int n = tid >> 4, c = tid & 15;
        float s0 = 0.f, s1 = 0.f, s2 = 0.f, s3 = 0.f;
        #pragma unroll 4
        for (int j = 0; j < 128; j += 4) {
            s0 += ow[n * 128 + j]     * Maggs[j][c];
            s1 += ow[n * 128 + j + 1] * Maggs[j + 1][c];
            s2 += ow[n * 128 + j + 2] * Maggs[j + 2][c];
            s3 += ow[n * 128 + j + 3] * Maggs[j + 3][c];
        }
        g_W2T[n * 144 + 128 + c] = __float2bfloat16((s0 + s1) + (s2 + s3));
    }
}

// ---------------- refine: warp-autonomous, barrier-free main loop -----------
__global__ __launch_bounds__(256, 2)
void refine_kernel(const float* __restrict__ logits, float* __restrict__ out,
                   const float* __restrict__ gatep) {
    // per-warp 16ch x 16px fp32 slabs, row stride 20 floats (conflict-free frag reads)
    __shared__ __align__(16) float wbuf[8][3][16 * 20];   // 30720 B
    __shared__ __align__(16) __nv_bfloat16 W1s[128][40];  // 10240 B
    __shared__ __align__(16) __nv_bfloat16 W2s[16][152];  //  4864 B
    __shared__ float c1s[128], c2s[16];                   //   576 B
    // total 46400 B < 48K; 2 CTAs/SM = 92.8K < 228K

    const int tid = threadIdx.x;
    const int lane = tid & 31;
    const int w = tid >> 5;
    const int t = lane & 3;
    const int g = lane >> 2;
    const int lr = lane >> 2;      // store/load row 0..7
    const int lc = lane & 3;       // 16B chunk 0..3

    for (int i = tid; i < 128 * 32; i += 256) W1s[i >> 5][i & 31] = g_W1T[i];
    for (int i = tid; i < 16 * 144; i += 256) W2s[i / 144][i % 144] = g_W2T[i];
    if (tid < 128) c1s[tid] = g_c1[tid];
    if (tid < 16)  c2s[tid] = g_c2[tid];
    const float gate = *gatep;
    __syncthreads();

    const int brow16 = (lane & 7) + ((lane >= 16) ? 8 : 0);
    const int bcol8 = (lane & 8) ? 8 : 0;
    uint32_t fW1[8][8];
    #pragma unroll
    for (int ntp = 0; ntp < 8; ntp++) {
        ldm4(fW1[ntp][0], fW1[ntp][1], fW1[ntp][2], fW1[ntp][3],
             sptr(&W1s[16 * ntp + brow16][bcol8]));
        ldm4(fW1[ntp][4], fW1[ntp][5], fW1[ntp][6], fW1[ntp][7],
             sptr(&W1s[16 * ntp + brow16][16 + bcol8]));
    }
    uint32_t fS[4];
    ldm4(fS[0], fS[1], fS[2], fS[3], sptr(&W2s[brow16][128 + bcol8]));
    const uint32_t w2base = sptr(&W2s[brow16][bcol8]);

    // per-warp cp.async prefetch: 16 rows x 64B, 2 instrs/lane
    auto prefetch = [&](int wt_, int bsel) {
        const int P = wt_ << 4;
        const float* __restrict__ src =
            logits + (size_t)(P >> 18) * (NC * HWSZ) + (P & (HWSZ - 1));
        const uint32_t d0 = sptr(&wbuf[w][bsel][lr * 20 + lc * 4]);
        const float* s0 = src + (size_t)lr * HWSZ + 4 * lc;
        asm volatile("cp.async.cg.shared.global [%0], [%1], 16;" :: "r"(d0), "l"(s0));
        asm volatile("cp.async.cg.shared.global [%0], [%1], 16;"
                     :: "r"(d0 + 8 * 20 * 4), "l"(s0 + (size_t)8 * HWSZ));
        asm volatile("cp.async.commit_group;");
    };

    int wt = (blockIdx.x << 3) | w;           // global warp id = first warp-tile
    prefetch(wt, 0);
    {
        int t1 = wt + NW; if (t1 >= WT_TOTAL) t1 = wt;
        prefetch(t1, 1);
    }
    int cb = 0;

    for (; wt < WT_TOTAL; wt += NW) {
        int n2 = wt + 2 * NW; if (n2 >= WT_TOTAL) n2 = wt;
        int nb = cb + 2; if (nb >= 3) nb -= 3;
        prefetch(n2, nb);                      // targets buffer last read 1 iter ago
        asm volatile("cp.async.wait_group 2;");
        __syncwarp();

        float* __restrict__ B = &wbuf[w][cb][0];

        // ---- softmax + A fragments ----
        uint32_t aL[4], aP[4];
        {
            const float l0 = B[(2 * t) * 20 + g],         l1 = B[(2 * t + 1) * 20 + g];
            const float l2 = B[(2 * t) * 20 + g + 8],     l3 = B[(2 * t + 1) * 20 + g + 8];
            const float l4 = B[(2 * t + 8) * 20 + g],     l5 = B[(2 * t + 9) * 20 + g];
            const float l6 = B[(2 * t + 8) * 20 + g + 8], l7 = B[(2 * t + 9) * 20 + g + 8];
            float mx = fmaxf(fmaxf(l0, l1), fmaxf(l4, l5));
            float my = fmaxf(fmaxf(l2, l3), fmaxf(l6, l7));
            mx = fmaxf(mx, __shfl_xor_sync(0xffffffffu, mx, 1));
            mx = fmaxf(mx, __shfl_xor_sync(0xffffffffu, mx, 2));
            my = fmaxf(my, __shfl_xor_sync(0xffffffffu, my, 1));
            my = fmaxf(my, __shfl_xor_sync(0xffffffffu, my, 2));
            const float p0 = __expf(l0 - mx), p1 = __expf(l1 - mx);
            const float p4 = __expf(l4 - mx), p5 = __expf(l5 - mx);
            const float q2 = __expf(l2 - my), q3 = __expf(l3 - my);
            const float q6 = __expf(l6 - my), q7 = __expf(l7 - my);
            float sx = (p0 + p1) + (p4 + p5);
            float sy = (q2 + q3) + (q6 + q7);
            sx += __shfl_xor_sync(0xffffffffu, sx, 1);
            sx += __shfl_xor_sync(0xffffffffu, sx, 2);
            sy += __shfl_xor_sync(0xffffffffu, sy, 1);
            sy += __shfl_xor_sync(0xffffffffu, sy, 2);
            const float ix = 1.0f / sx, iy = 1.0f / sy;
            aL[0] = pack2(l0, l1); aL[1] = pack2(l2, l3);
            aL[2] = pack2(l4, l5); aL[3] = pack2(l6, l7);
            aP[0] = pack2(p0 * ix, p1 * ix); aP[1] = pack2(q2 * iy, q3 * iy);
            aP[2] = pack2(p4 * ix, p5 * ix); aP[3] = pack2(q6 * iy, q7 * iy);
        }

        // ---- interleaved GEMM1 -> relu -> GEMM2 ----
        float racc[2][4];
        #pragma unroll
        for (int nt = 0; nt < 2; nt++) {
            const float bv0 = c2s[8 * nt + 2 * t];
            const float bv1 = c2s[8 * nt + 2 * t + 1];
            racc[nt][0] = bv0; racc[nt][1] = bv1; racc[nt][2] = bv0; racc[nt][3] = bv1;
        }
        mma16816(racc[0], aP, fS[0], fS[1]);
        mma16816(racc[1], aP, fS[2], fS[3]);
        #pragma unroll
        for (int kb = 0; kb < 8; kb++) {
            uint32_t b0, b1, b2, b3;
            ldm4(b0, b1, b2, b3, w2base + 32 * kb);
            float acc0[4], acc1[4];
            {
                const float a00 = c1s[16 * kb + 2 * t];
                const float a01 = c1s[16 * kb + 2 * t + 1];
                const float a10 = c1s[16 * kb + 8 + 2 * t];
                const float a11 = c1s[16 * kb + 8 + 2 * t + 1];
                acc0[0] = a00; acc0[1] = a01; acc0[2] = a00; acc0[3] = a01;
                acc1[0] = a10; acc1[1] = a11; acc1[2] = a10; acc1[3] = a11;
            }
            mma16816(acc0, aL, fW1[kb][0], fW1[kb][1]);
            mma16816(acc1, aL, fW1[kb][2], fW1[kb][3]);
            mma16816(acc0, aP, fW1[kb][4], fW1[kb][5]);
            mma16816(acc1, aP, fW1[kb][6], fW1[kb][7]);
            uint32_t h[4];
            h[0] = packrelu2(acc0[0], acc0[1]);
            h[1] = packrelu2(acc0[2], acc0[3]);
            h[2] = packrelu2(acc1[0], acc1[1]);
            h[3] = packrelu2(acc1[2], acc1[3]);
            mma16816(racc[0], h, b0, b1);
            mma16816(racc[1], h, b2, b3);
        }

        // ---- epilogue: in-place gate*r + residual (lane-owned cells) ----
        B[(2 * t) * 20 + g]         = fmaf(gate, racc[0][0], B[(2 * t) * 20 + g]);
        B[(2 * t + 1) * 20 + g]     = fmaf(gate, racc[0][1], B[(2 * t + 1) * 20 + g]);
        B[(2 * t) * 20 + g + 8]     = fmaf(gate, racc[0][2], B[(2 * t) * 20 + g + 8]);
        B[(2 * t + 1) * 20 + g + 8] = fmaf(gate, racc[0][3], B[(2 * t + 1) * 20 + g + 8]);
        B[(2 * t + 8) * 20 + g]     = fmaf(gate, racc[1][0], B[(2 * t + 8) * 20 + g]);
        B[(2 * t + 9) * 20 + g]     = fmaf(gate, racc[1][1], B[(2 * t + 9) * 20 + g]);
        B[(2 * t + 8) * 20 + g + 8] = fmaf(gate, racc[1][2], B[(2 * t + 8) * 20 + g + 8]);
        B[(2 * t + 9) * 20 + g + 8] = fmaf(gate, racc[1][3], B[(2 * t + 9) * 20 + g + 8]);
        __syncwarp();

        // ---- per-warp store: 16 rows x 64B ----
        {
            const int P = wt << 4;
            float* __restrict__ dst =
                out + (size_t)(P >> 18) * (NC * HWSZ) + (P & (HWSZ - 1));
            const float4 v0 = *reinterpret_cast<const float4*>(B + lr * 20 + 4 * lc);
            const float4 v1 = *reinterpret_cast<const float4*>(B + (lr + 8) * 20 + 4 * lc);
            *reinterpret_cast<float4*>(dst + (size_t)lr * HWSZ + 4 * lc) = v0;
            *reinterpret_cast<float4*>(dst + (size_t)(lr + 8) * HWSZ + 4 * lc) = v1;
        }
        cb = cb + 1; if (cb >= 3) cb = 0;
    }
}

// ---------------- launch -----------------------------------------------------
extern "C" void kernel_launch(void* const* d_in, const int* in_sizes, int n_in,
                              void* d_out, int out_size) {
    const float* logits = (const float*)d_in[0];
    const float* E      = (const float*)d_in[1];
    const float* aw1    = (const float*)d_in[2];
    const float* ab1    = (const float*)d_in[3];
    const float* aw2    = (const float*)d_in[4];
    const float* ab2    = (const float*)d_in[5];
    const float* w0     = (const float*)d_in[6];
    const float* b0     = (const float*)d_in[7];
    const float* w1     = (const float*)d_in[8];
    const float* b1     = (const float*)d_in[9];
    const float* fw     = (const float*)d_in[10];
    const float* fb     = (const float*)d_in[11];
    const float* ow     = (const float*)d_in[12];
    const float* ob     = (const float*)d_in[13];
    const float* gate   = (const float*)d_in[14];
    float* out = (float*)d_out;

    setup_x<<<337, 256>>>(E, aw1, ab1, aw2, ab2, w0, b0, w1, b1, fw, fb, ow, ob);
    setup_y<<<1, 256>>>(E, ow);
    refine_kernel<<<GRID, 256>>>(logits, out, gate);
}